// round 5
// baseline (speedup 1.0000x reference)
#include <cuda_runtime.h>
#include <math.h>

// ---------------- problem constants ----------------
static const int NTOK   = 8192;   // N
static const int DMODEL = 512;    // D
static const int NHEADS = 8;
static const int DHEAD  = 64;
static const int MLAND  = 256;    // M landmarks
static const int LFOLD  = 32;     // N / M
static const int WPD    = 256;    // weight_params_dim
static const int NEDGE  = 262144; // E
static const int KCONV  = 33;
static const int QKVW   = 3 * NHEADS * DHEAD; // 1536
static const int PITERS = 6;

// ---------------- device scratch (BSS) ----------------
__device__ float g_qkv [NTOK * QKVW];
__device__ float g_ql  [NHEADS * MLAND * DHEAD];
__device__ float g_kl  [NHEADS * MLAND * DHEAD];
__device__ float g_a1  [(long)NHEADS * NTOK * MLAND];
__device__ float g_a2  [NHEADS * MLAND * MLAND];
__device__ float g_a3  [(long)NHEADS * MLAND * NTOK];
__device__ float g_z   [NHEADS * MLAND * MLAND];
__device__ float g_z2  [NHEADS * MLAND * MLAND];
__device__ float g_xz  [NHEADS * MLAND * MLAND];
__device__ float g_t1  [NHEADS * MLAND * MLAND];
__device__ float g_t2  [NHEADS * MLAND * MLAND];
__device__ float g_a3v [NHEADS * MLAND * DHEAD];
__device__ float g_w1  [(long)NHEADS * NTOK * MLAND];
__device__ float g_xh  [NTOK * DMODEL];
__device__ float g_xg  [NTOK * DMODEL];
__device__ float g_enc [NTOK * DMODEL];
__device__ float g_val [NTOK * DMODEL];
__device__ float g_qe  [NTOK * WPD];
__device__ float g_ke  [NTOK * WPD];
__device__ float g_Araw [NTOK];
__device__ float g_alpha[NTOK];
__device__ unsigned int g_norm[2];

// ---------------- tf32 helpers ----------------
__device__ __forceinline__ unsigned f2tf(float x) {
    unsigned u;
    asm("cvt.rna.tf32.f32 %0, %1;" : "=r"(u) : "f"(x));
    return u;
}
__device__ __forceinline__ void split_tf(float x, unsigned& hi, unsigned& lo) {
    hi = f2tf(x);
    lo = f2tf(x - __uint_as_float(hi));
}
__device__ __forceinline__ void mma8(float* c, const unsigned* a, const unsigned* b) {
    asm volatile(
        "mma.sync.aligned.m16n8k8.row.col.f32.tf32.tf32.f32 "
        "{%0,%1,%2,%3}, {%4,%5,%6,%7}, {%8,%9}, {%0,%1,%2,%3};"
        : "+f"(c[0]), "+f"(c[1]), "+f"(c[2]), "+f"(c[3])
        : "r"(a[0]), "r"(a[1]), "r"(a[2]), "r"(a[3]), "r"(b[0]), "r"(b[1]));
}

// fragment-order smem index helpers (m16n8k8)
// A value (row-in-16 r', col-in-8 c): thread t=(r'&7)*4+(c&3), v=(r'>>3)+2*(c>>2)
// B value (krow-in-8 k', ncol-in-8 n'): thread t=n'*4+(k'&3), v=k'>>2

// =====================================================================
// gemmT: tf32x3 tensor-core GEMM. C = alpha*A@op(B) + diag*I (optional C2).
// 128x128x16 CTA tile, 256 threads (8 warps as 4x2), warp tile 32x64.
// REQUIRES: M%128==0, N%128==0, K%16==0, 16B-aligned rows.
// TB: B is [N,K] row-major. !TB: B is [K,N].
// =====================================================================
template<bool TB>
__global__ __launch_bounds__(256, 2)
void gemmT_k(int M, int N, int K, float alpha,
             const float* __restrict__ A, int lda, long sA,
             const float* __restrict__ B, int ldb, long sB,
             float* __restrict__ C, int ldc, long sC,
             float diag, float* __restrict__ C2, float alpha2, float diag2)
{
    A += (long)blockIdx.z * sA;
    B += (long)blockIdx.z * sB;
    C += (long)blockIdx.z * sC;
    if (C2) C2 += (long)blockIdx.z * sC;
    const int row0 = blockIdx.y * 128;
    const int col0 = blockIdx.x * 128;

    __shared__ __align__(16) unsigned Ah[2048], Al[2048], Bh[2048], Bl[2048];

    const int tid  = threadIdx.x;
    const int lane = tid & 31;
    const int w    = tid >> 5;
    const int wr   = w >> 1;   // 0..3
    const int wc   = w & 1;    // 0..1

    const float* Ap = A + (long)(row0 + (tid >> 1)) * lda + (tid & 1) * 8;
    const float* Bp = TB ? (B + (long)(col0 + (tid >> 1)) * ldb + (tid & 1) * 8)
                         : (B + (long)(tid >> 4) * ldb + col0 + (tid & 15) * 8);

    float4 ra0, ra1, rb0, rb1;
    auto loadG = [&](int k0) {
        ra0 = *(const float4*)(Ap + k0);
        ra1 = *(const float4*)(Ap + k0 + 4);
        if (TB) {
            rb0 = *(const float4*)(Bp + k0);
            rb1 = *(const float4*)(Bp + k0 + 4);
        } else {
            rb0 = *(const float4*)(Bp + (long)k0 * ldb);
            rb1 = *(const float4*)(Bp + (long)k0 * ldb + 4);
        }
    };

    auto stsA = [&](float x, int r, int k) {
        int rt = r >> 4, rr = r & 15, kt = k >> 3, c = k & 7;
        int t = (rr & 7) * 4 + (c & 3);
        int v = (rr >> 3) + ((c >> 2) << 1);
        int idx = ((rt * 32 + t) * 2 + kt) * 4 + v;
        unsigned hi, lo; split_tf(x, hi, lo);
        Ah[idx] = hi; Al[idx] = lo;
    };
    auto stsB = [&](float x, int n, int k) {
        int nt = n >> 3, nn = n & 7, kt = k >> 3, kk = k & 7;
        int t = nn * 4 + (kk & 3);
        int v = kk >> 2;
        int idx = ((nt * 32 + t) * 2 + kt) * 2 + v;
        unsigned hi, lo; split_tf(x, hi, lo);
        Bh[idx] = hi; Bl[idx] = lo;
    };
    auto stsAll = [&]() {
        int r = tid >> 1, ks = (tid & 1) * 8;
        stsA(ra0.x, r, ks + 0); stsA(ra0.y, r, ks + 1);
        stsA(ra0.z, r, ks + 2); stsA(ra0.w, r, ks + 3);
        stsA(ra1.x, r, ks + 4); stsA(ra1.y, r, ks + 5);
        stsA(ra1.z, r, ks + 6); stsA(ra1.w, r, ks + 7);
        if (TB) {
            int n = tid >> 1;
            stsB(rb0.x, n, ks + 0); stsB(rb0.y, n, ks + 1);
            stsB(rb0.z, n, ks + 2); stsB(rb0.w, n, ks + 3);
            stsB(rb1.x, n, ks + 4); stsB(rb1.y, n, ks + 5);
            stsB(rb1.z, n, ks + 6); stsB(rb1.w, n, ks + 7);
        } else {
            int k = tid >> 4, ns = (tid & 15) * 8;
            stsB(rb0.x, ns + 0, k); stsB(rb0.y, ns + 1, k);
            stsB(rb0.z, ns + 2, k); stsB(rb0.w, ns + 3, k);
            stsB(rb1.x, ns + 4, k); stsB(rb1.y, ns + 5, k);
            stsB(rb1.z, ns + 6, k); stsB(rb1.w, ns + 7, k);
        }
    };

    float acc[2][8][4];
    #pragma unroll
    for (int i = 0; i < 2; i++)
        #pragma unroll
        for (int j = 0; j < 8; j++)
            #pragma unroll
            for (int v = 0; v < 4; v++) acc[i][j][v] = 0.f;

    auto compute = [&]() {
        #pragma unroll
        for (int kt = 0; kt < 2; kt++) {
            unsigned afh[2][4], afl[2][4];
            #pragma unroll
            for (int r2 = 0; r2 < 2; r2++) {
                int rt = wr * 2 + r2;
                *(uint4*)afh[r2] = *(const uint4*)&Ah[(rt * 32 + lane) * 8 + kt * 4];
                *(uint4*)afl[r2] = *(const uint4*)&Al[(rt * 32 + lane) * 8 + kt * 4];
            }
            #pragma unroll
            for (int n2 = 0; n2 < 8; n2++) {
                int nt = wc * 8 + n2;
                unsigned bfh[2], bfl[2];
                *(uint2*)bfh = *(const uint2*)&Bh[(nt * 32 + lane) * 4 + kt * 2];
                *(uint2*)bfl = *(const uint2*)&Bl[(nt * 32 + lane) * 4 + kt * 2];
                #pragma unroll
                for (int r2 = 0; r2 < 2; r2++) {
                    mma8(acc[r2][n2], afh[r2], bfh);
                    mma8(acc[r2][n2], afl[r2], bfh);
                    mma8(acc[r2][n2], afh[r2], bfl);
                }
            }
        }
    };

    loadG(0);
    for (int k0 = 0; k0 < K; k0 += 16) {
        __syncthreads();
        stsAll();
        __syncthreads();
        if (k0 + 16 < K) loadG(k0 + 16);
        compute();
    }

    const int g = lane >> 2, tg = lane & 3;
    #pragma unroll
    for (int r2 = 0; r2 < 2; r2++) {
        #pragma unroll
        for (int n2 = 0; n2 < 8; n2++) {
            int gr = row0 + wr * 32 + r2 * 16 + g;
            int gc = col0 + wc * 64 + n2 * 8 + tg * 2;
            float* c = acc[r2][n2];
            float* p0 = C + (long)gr * ldc + gc;
            float* p1 = C + (long)(gr + 8) * ldc + gc;
            float d00 = (gr == gc) ? 1.f : 0.f;
            float d01 = (gr == gc + 1) ? 1.f : 0.f;
            float d10 = (gr + 8 == gc) ? 1.f : 0.f;
            float d11 = (gr + 8 == gc + 1) ? 1.f : 0.f;
            p0[0] = alpha * c[0] + diag * d00;
            p0[1] = alpha * c[1] + diag * d01;
            p1[0] = alpha * c[2] + diag * d10;
            p1[1] = alpha * c[3] + diag * d11;
            if (C2) {
                float* q0 = C2 + (long)gr * ldc + gc;
                float* q1 = C2 + (long)(gr + 8) * ldc + gc;
                q0[0] = alpha2 * c[0] + diag2 * d00;
                q0[1] = alpha2 * c[1] + diag2 * d01;
                q1[0] = alpha2 * c[2] + diag2 * d10;
                q1[1] = alpha2 * c[3] + diag2 * d11;
            }
        }
    }
}

static void gemmT(bool tb, int M, int N, int K, float alpha,
                  const float* A, int lda, long sA,
                  const float* B, int ldb, long sB,
                  float* C, int ldc, long sC, int batch,
                  float diag = 0.f, float* C2 = nullptr,
                  float alpha2 = 0.f, float diag2 = 0.f)
{
    dim3 g(N / 128, M / 128, batch);
    if (tb) gemmT_k<true ><<<g, 256>>>(M, N, K, alpha, A, lda, sA, B, ldb, sB,
                                       C, ldc, sC, diag, C2, alpha2, diag2);
    else    gemmT_k<false><<<g, 256>>>(M, N, K, alpha, A, lda, sA, B, ldb, sB,
                                       C, ldc, sC, diag, C2, alpha2, diag2);
}

// =====================================================================
// gemmT64: tf32x3, 128x64x16 CTA tile (N=64 GEMMs), NT only (B=[K,N]).
// 8 warps as 4x2, warp tile 32x32. Optional split-K via atomicAdd.
// =====================================================================
__global__ __launch_bounds__(256, 2)
void gemmT64_k(int M, int K, float alpha,
               const float* __restrict__ A, int lda, long sA,
               const float* __restrict__ B, int ldb, long sB,
               float* __restrict__ C, int ldc, long sC, int kSplit)
{
    int bz = blockIdx.z;
    int batch = bz / kSplit, ks = bz - batch * kSplit;
    A += (long)batch * sA;
    B += (long)batch * sB;
    C += (long)batch * sC;
    int chunk = K / kSplit;
    int k0s = ks * chunk, k1 = k0s + chunk;

    const int row0 = blockIdx.y * 128;

    __shared__ __align__(16) unsigned Ah[2048], Al[2048], Bh[1024], Bl[1024];

    const int tid  = threadIdx.x;
    const int lane = tid & 31;
    const int w    = tid >> 5;
    const int wr   = w >> 1;   // 0..3
    const int wc   = w & 1;    // 0..1

    const float* Ap = A + (long)(row0 + (tid >> 1)) * lda + (tid & 1) * 8;
    const float* Bp = B + (long)(tid >> 4) * ldb + (tid & 15) * 4;

    float4 ra0, ra1, rb0;
    auto loadG = [&](int k0) {
        ra0 = *(const float4*)(Ap + k0);
        ra1 = *(const float4*)(Ap + k0 + 4);
        rb0 = *(const float4*)(Bp + (long)k0 * ldb);
    };
    auto stsA = [&](float x, int r, int k) {
        int rt = r >> 4, rr = r & 15, kt = k >> 3, c = k & 7;
        int t = (rr & 7) * 4 + (c & 3);
        int v = (rr >> 3) + ((c >> 2) << 1);
        int idx = ((rt * 32 + t) * 2 + kt) * 4 + v;
        unsigned hi, lo; split_tf(x, hi, lo);
        Ah[idx] = hi; Al[idx] = lo;
    };
    auto stsB = [&](float x, int n, int k) {
        int nt = n >> 3, nn = n & 7, kt = k >> 3, kk = k & 7;
        int t = nn * 4 + (kk & 3);
        int v = kk >> 2;
        int idx = ((nt * 32 + t) * 2 + kt) * 2 + v;
        unsigned hi, lo; split_tf(x, hi, lo);
        Bh[idx] = hi; Bl[idx] = lo;
    };
    auto stsAll = [&]() {
        int r = tid >> 1, kks = (tid & 1) * 8;
        stsA(ra0.x, r, kks + 0); stsA(ra0.y, r, kks + 1);
        stsA(ra0.z, r, kks + 2); stsA(ra0.w, r, kks + 3);
        stsA(ra1.x, r, kks + 4); stsA(ra1.y, r, kks + 5);
        stsA(ra1.z, r, kks + 6); stsA(ra1.w, r, kks + 7);
        int k = tid >> 4, ns = (tid & 15) * 4;
        stsB(rb0.x, ns + 0, k); stsB(rb0.y, ns + 1, k);
        stsB(rb0.z, ns + 2, k); stsB(rb0.w, ns + 3, k);
    };

    float acc[2][4][4];
    #pragma unroll
    for (int i = 0; i < 2; i++)
        #pragma unroll
        for (int j = 0; j < 4; j++)
            #pragma unroll
            for (int v = 0; v < 4; v++) acc[i][j][v] = 0.f;

    auto compute = [&]() {
        #pragma unroll
        for (int kt = 0; kt < 2; kt++) {
            unsigned afh[2][4], afl[2][4];
            #pragma unroll
            for (int r2 = 0; r2 < 2; r2++) {
                int rt = wr * 2 + r2;
                *(uint4*)afh[r2] = *(const uint4*)&Ah[(rt * 32 + lane) * 8 + kt * 4];
                *(uint4*)afl[r2] = *(const uint4*)&Al[(rt * 32 + lane) * 8 + kt * 4];
            }
            #pragma unroll
            for (int n2 = 0; n2 < 4; n2++) {
                int nt = wc * 4 + n2;
                unsigned bfh[2], bfl[2];
                *(uint2*)bfh = *(const uint2*)&Bh[(nt * 32 + lane) * 4 + kt * 2];
                *(uint2*)bfl = *(const uint2*)&Bl[(nt * 32 + lane) * 4 + kt * 2];
                #pragma unroll
                for (int r2 = 0; r2 < 2; r2++) {
                    mma8(acc[r2][n2], afh[r2], bfh);
                    mma8(acc[r2][n2], afl[r2], bfh);
                    mma8(acc[r2][n2], afh[r2], bfl);
                }
            }
        }
    };

    loadG(k0s);
    for (int k0 = k0s; k0 < k1; k0 += 16) {
        __syncthreads();
        stsAll();
        __syncthreads();
        if (k0 + 16 < k1) loadG(k0 + 16);
        compute();
    }

    const int g = lane >> 2, tg = lane & 3;
    #pragma unroll
    for (int r2 = 0; r2 < 2; r2++) {
        #pragma unroll
        for (int n2 = 0; n2 < 4; n2++) {
            int gr = row0 + wr * 32 + r2 * 16 + g;
            int gc = wc * 32 + n2 * 8 + tg * 2;
            float* c = acc[r2][n2];
            float* p0 = C + (long)gr * ldc + gc;
            float* p1 = C + (long)(gr + 8) * ldc + gc;
            if (kSplit > 1) {
                atomicAdd(p0 + 0, alpha * c[0]); atomicAdd(p0 + 1, alpha * c[1]);
                atomicAdd(p1 + 0, alpha * c[2]); atomicAdd(p1 + 1, alpha * c[3]);
            } else {
                p0[0] = alpha * c[0]; p0[1] = alpha * c[1];
                p1[0] = alpha * c[2]; p1[1] = alpha * c[3];
            }
        }
    }
}

// =====================================================================
// gemm64ep: fp32 SIMT 256x256x256 batched GEMM (pinv), NT, 64x64 tile,
// fused epilogue:  C = alpha*(A@B) + diag*I,  optional C2 likewise.
// =====================================================================
__global__ __launch_bounds__(256)
void gemm64ep_k(float alpha, float diag,
                const float* __restrict__ A, const float* __restrict__ B,
                float* __restrict__ C,
                float alpha2, float diag2, float* __restrict__ C2)
{
    const long sb = (long)MLAND * MLAND;
    A += blockIdx.z * sb;
    B += blockIdx.z * sb;
    C += blockIdx.z * sb;
    if (C2) C2 += blockIdx.z * sb;

    __shared__ float As[64 * 17];
    __shared__ float Bs[16 * 64];

    int tid = threadIdx.x;
    int row0 = blockIdx.y * 64;
    int col0 = blockIdx.x * 64;
    int tx = tid & 15, ty = tid >> 4;

    float acc[4][4] = {};

    for (int kk = 0; kk < 256; kk += 16) {
        #pragma unroll
        for (int i = 0; i < 4; i++) {
            int e = tid + i * 256;
            int r = e >> 4, c = e & 15;
            As[r * 17 + c] = A[(long)(row0 + r) * 256 + kk + c];
        }
        #pragma unroll
        for (int i = 0; i < 4; i++) {
            int e = tid + i * 256;
            int c = e >> 6, n = e & 63;
            Bs[c * 64 + n] = B[(long)(kk + c) * 256 + col0 + n];
        }
        __syncthreads();
        #pragma unroll
        for (int c = 0; c < 16; c++) {
            float a[4], b[4];
            #pragma unroll
            for (int i = 0; i < 4; i++) a[i] = As[(ty * 4 + i) * 17 + c];
            #pragma unroll
            for (int j = 0; j < 4; j++) b[j] = Bs[c * 64 + tx * 4 + j];
            #pragma unroll
            for (int i = 0; i < 4; i++)
                #pragma unroll
                for (int j = 0; j < 4; j++)
                    acc[i][j] = fmaf(a[i], b[j], acc[i][j]);
        }
        __syncthreads();
    }
    #pragma unroll
    for (int i = 0; i < 4; i++) {
        int gr = row0 + ty * 4 + i;
        #pragma unroll
        for (int j = 0; j < 4; j++) {
            int gc = col0 + tx * 4 + j;
            float d = (gr == gc) ? 1.f : 0.f;
            C[(long)gr * 256 + gc] = alpha * acc[i][j] + diag * d;
            if (C2) C2[(long)gr * 256 + gc] = alpha2 * acc[i][j] + diag2 * d;
        }
    }
}

// ---------------- small kernels ----------------
__global__ void zeros_k(float* a3v, float* Araw, unsigned int* norm)
{
    long i = (long)blockIdx.x * 256 + threadIdx.x;
    if (i < NHEADS * MLAND * DHEAD) a3v[i] = 0.f;
    if (i < NTOK) Araw[i] = 0.f;
    if (i < 2) norm[i] = 0u;
}

__global__ void landmarks_k(const float* __restrict__ qkv,
                            float* __restrict__ ql, float* __restrict__ kl)
{
    int idx = blockIdx.x * blockDim.x + threadIdx.x;
    if (idx >= NHEADS * MLAND * DHEAD) return;
    int d = idx & 63; int j = (idx >> 6) & 255; int h = idx >> 14;
    const float* qp = qkv + (long)(j * LFOLD) * QKVW + h * DHEAD + d;
    const float* kp = qp + NHEADS * DHEAD;
    float sq = 0.f, sk = 0.f;
    #pragma unroll 4
    for (int t = 0; t < LFOLD; t++) {
        sq += qp[(long)t * QKVW];
        sk += kp[(long)t * QKVW];
    }
    ql[idx] = sq * (1.f / LFOLD);
    kl[idx] = sk * (1.f / LFOLD);
}

__global__ __launch_bounds__(256)
void softmax256_k(float* __restrict__ X)
{
    float* x = X + (long)blockIdx.x * 256;
    int tid = threadIdx.x;
    __shared__ float sm[8];
    float v = x[tid];
    float m = v;
    #pragma unroll
    for (int o = 16; o; o >>= 1) m = fmaxf(m, __shfl_xor_sync(0xffffffffu, m, o));
    if ((tid & 31) == 0) sm[tid >> 5] = m;
    __syncthreads();
    m = sm[0];
    #pragma unroll
    for (int i = 1; i < 8; i++) m = fmaxf(m, sm[i]);
    float e = __expf(v - m);
    float s = e;
    #pragma unroll
    for (int o = 16; o; o >>= 1) s += __shfl_xor_sync(0xffffffffu, s, o);
    __syncthreads();
    if ((tid & 31) == 0) sm[tid >> 5] = s;
    __syncthreads();
    s = sm[0];
    #pragma unroll
    for (int i = 1; i < 8; i++) s += sm[i];
    x[tid] = e * (1.f / s);
}

__global__ __launch_bounds__(1024)
void softmax8192_k(float* __restrict__ X)
{
    float* x = X + (long)blockIdx.x * 8192;
    int tid = threadIdx.x;
    __shared__ float sm[32];
    float4 v0 = *(const float4*)(x + tid * 8);
    float4 v1 = *(const float4*)(x + tid * 8 + 4);
    float m = fmaxf(fmaxf(fmaxf(v0.x, v0.y), fmaxf(v0.z, v0.w)),
                    fmaxf(fmaxf(v1.x, v1.y), fmaxf(v1.z, v1.w)));
    #pragma unroll
    for (int o = 16; o; o >>= 1) m = fmaxf(m, __shfl_xor_sync(0xffffffffu, m, o));
    if ((tid & 31) == 0) sm[tid >> 5] = m;
    __syncthreads();
    m = sm[0];
    #pragma unroll
    for (int i = 1; i < 32; i++) m = fmaxf(m, sm[i]);
    float e0 = __expf(v0.x - m), e1 = __expf(v0.y - m);
    float e2 = __expf(v0.z - m), e3 = __expf(v0.w - m);
    float e4 = __expf(v1.x - m), e5 = __expf(v1.y - m);
    float e6 = __expf(v1.z - m), e7 = __expf(v1.w - m);
    float s = ((e0 + e1) + (e2 + e3)) + ((e4 + e5) + (e6 + e7));
    #pragma unroll
    for (int o = 16; o; o >>= 1) s += __shfl_xor_sync(0xffffffffu, s, o);
    __syncthreads();
    if ((tid & 31) == 0) sm[tid >> 5] = s;
    __syncthreads();
    s = sm[0];
    #pragma unroll
    for (int i = 1; i < 32; i++) s += sm[i];
    float inv = 1.f / s;
    *(float4*)(x + tid * 8)     = make_float4(e0 * inv, e1 * inv, e2 * inv, e3 * inv);
    *(float4*)(x + tid * 8 + 4) = make_float4(e4 * inv, e5 * inv, e6 * inv, e7 * inv);
}

__global__ void a2norm_k(const float* __restrict__ a2, unsigned int* norm)
{
    int h = blockIdx.x; int t = threadIdx.x;
    const float* x = a2 + (long)h * MLAND * MLAND;
    float rs = 0.f, cs = 0.f;
    for (int j = 0; j < MLAND; j++) {
        rs += fabsf(x[t * MLAND + j]);
        cs += fabsf(x[j * MLAND + t]);
    }
    __shared__ float s1[8], s2[8];
    for (int o = 16; o; o >>= 1) {
        rs = fmaxf(rs, __shfl_xor_sync(0xffffffffu, rs, o));
        cs = fmaxf(cs, __shfl_xor_sync(0xffffffffu, cs, o));
    }
    if ((t & 31) == 0) { s1[t >> 5] = rs; s2[t >> 5] = cs; }
    __syncthreads();
    if (t == 0) {
        rs = s1[0]; cs = s2[0];
        for (int w = 1; w < 8; w++) { rs = fmaxf(rs, s1[w]); cs = fmaxf(cs, s2[w]); }
        atomicMax(&norm[0], __float_as_uint(rs));
        atomicMax(&norm[1], __float_as_uint(cs));
    }
}

__global__ void zinit_k(const float* __restrict__ a2, float* __restrict__ z,
                        const unsigned int* __restrict__ norm)
{
    long idx = (long)blockIdx.x * 256 + threadIdx.x;
    if (idx >= (long)NHEADS * MLAND * MLAND) return;
    float inv = 1.f / (__uint_as_float(norm[0]) * __uint_as_float(norm[1]));
    int j = idx & 255; int i = (idx >> 8) & 255; long h = idx >> 16;
    z[idx] = a2[h * 65536 + (long)j * 256 + i] * inv;
}

__global__ void convadd_k(const float* __restrict__ qkv,
                          const float* __restrict__ rker,
                          float* __restrict__ xh)
{
    long idx = (long)blockIdx.x * 256 + threadIdx.x;
    if (idx >= (long)NTOK * DMODEL) return;
    int col = idx & 511; long n = idx >> 9;
    int h = col >> 6;
    float s = 0.f;
    #pragma unroll
    for (int t = 0; t < KCONV; t++) {
        long r = n + t - KCONV / 2;
        if (r >= 0 && r < NTOK)
            s += rker[h * KCONV + t] * qkv[r * QKVW + 2 * NHEADS * DHEAD + col];
    }
    xh[idx] += s;
}

__global__ void enc_k(const float* __restrict__ xg, const float* __restrict__ bout,
                      const float* __restrict__ dense, float* __restrict__ enc)
{
    long idx = (long)blockIdx.x * 256 + threadIdx.x;
    if (idx >= (long)NTOK * DMODEL) return;
    int col = idx & 511;
    enc[idx] = xg[idx] + bout[col] + dense[idx];
}

__global__ void edge_k(const float* __restrict__ qe, const float* __restrict__ ke,
                       const int* __restrict__ rows, const int* __restrict__ cols,
                       const float* __restrict__ vals, float* __restrict__ Araw)
{
    int e = blockIdx.x * (blockDim.x >> 5) + (threadIdx.x >> 5);
    int lane = threadIdx.x & 31;
    if (e >= NEDGE) return;
    int r = rows[e], c = cols[e];
    const float4* qr = (const float4*)(qe + (long)r * WPD);
    const float4* kc = (const float4*)(ke + (long)c * WPD);
    float s = 0.f;
    #pragma unroll
    for (int i = lane; i < WPD / 4; i += 32) {
        float4 a = qr[i], b = kc[i];
        s += a.x * b.x + a.y * b.y + a.z * b.z + a.w * b.w;
    }
    for (int o = 16; o; o >>= 1) s += __shfl_xor_sync(0xffffffffu, s, o);
    if (lane == 0) atomicAdd(&Araw[r], s * 0.0625f * vals[e]);
}

__global__ void softmax_all_k(const float* __restrict__ A, float* __restrict__ alpha, int n)
{
    __shared__ float sm[32];
    int tid = threadIdx.x; // 1024
    float m = -1e30f;
    for (int i = tid; i < n; i += 1024) m = fmaxf(m, A[i]);
    for (int o = 16; o; o >>= 1) m = fmaxf(m, __shfl_xor_sync(0xffffffffu, m, o));
    if ((tid & 31) == 0) sm[tid >> 5] = m;
    __syncthreads();
    if (tid == 0) { float bm = sm[0]; for (int w = 1; w < 32; w++) bm = fmaxf(bm, sm[w]); sm[0] = bm; }
    __syncthreads();
    m = sm[0];
    __syncthreads();
    float s = 0.f;
    for (int i = tid; i < n; i += 1024) s += __expf(A[i] - m);
    for (int o = 16; o; o >>= 1) s += __shfl_xor_sync(0xffffffffu, s, o);
    if ((tid & 31) == 0) sm[tid >> 5] = s;
    __syncthreads();
    if (tid == 0) { float bs = 0.f; for (int w = 0; w < 32; w++) bs += sm[w]; sm[0] = bs; }
    __syncthreads();
    float inv = 1.f / sm[0];
    for (int i = tid; i < n; i += 1024) alpha[i] = __expf(A[i] - m) * inv;
}

__global__ void final_k(const float* __restrict__ val, const float* __restrict__ wvb,
                        const float* __restrict__ alpha, const float* __restrict__ enc,
                        const float* __restrict__ Araw, float* __restrict__ out)
{
    long idx = (long)blockIdx.x * 256 + threadIdx.x;
    long total = (long)NTOK * DMODEL;
    if (idx < total) {
        int col = idx & 511; long n = idx >> 9;
        float v = val[idx] + wvb[col];
        float xl = alpha[n] * v;
        float w = 1.f / (1.f + __expf(xl)); // sigmoid(-xl)
        float sq = w * w;
        float e = enc[idx];
        out[idx] = xl * 2.f * sq + 2.f * e * (1.f - sq);
    }
    if (idx < NTOK) out[total + idx] = Araw[idx];
}

// ---------------- driver ----------------
extern "C" void kernel_launch(void* const* d_in, const int* in_sizes, int n_in,
                              void* d_out, int out_size)
{
    const float* dense  = (const float*)d_in[0];
    const int*   arows  = (const int*)  d_in[1];
    const int*   acols  = (const int*)  d_in[2];
    const float* avals  = (const float*)d_in[3];
    const float* wq     = (const float*)d_in[4];
    const float* wk     = (const float*)d_in[5];
    const float* w_qkv  = (const float*)d_in[6];
    const float* w_out  = (const float*)d_in[7];
    const float* b_out  = (const float*)d_in[8];
    const float* rker   = (const float*)d_in[9];
    const float* wv_w   = (const float*)d_in[10];
    const float* wv_b   = (const float*)d_in[11];
    float* out = (float*)d_out;

    float *qkv, *ql, *kl, *a1, *a2, *a3, *z, *z2, *xz, *t1, *t2, *a3v, *w1;
    float *xh, *xg, *enc, *val, *qe, *ke, *Araw, *alpha;
    unsigned int* norm;
    cudaGetSymbolAddress((void**)&qkv, g_qkv);
    cudaGetSymbolAddress((void**)&ql,  g_ql);
    cudaGetSymbolAddress((void**)&kl,  g_kl);
    cudaGetSymbolAddress((void**)&a1,  g_a1);
    cudaGetSymbolAddress((void**)&a2,  g_a2);
    cudaGetSymbolAddress((void**)&a3,  g_a3);
    cudaGetSymbolAddress((void**)&z,   g_z);
    cudaGetSymbolAddress((void**)&z2,  g_z2);
    cudaGetSymbolAddress((void**)&xz,  g_xz);
    cudaGetSymbolAddress((void**)&t1,  g_t1);
    cudaGetSymbolAddress((void**)&t2,  g_t2);
    cudaGetSymbolAddress((void**)&a3v, g_a3v);
    cudaGetSymbolAddress((void**)&w1,  g_w1);
    cudaGetSymbolAddress((void**)&xh,  g_xh);
    cudaGetSymbolAddress((void**)&xg,  g_xg);
    cudaGetSymbolAddress((void**)&enc, g_enc);
    cudaGetSymbolAddress((void**)&val, g_val);
    cudaGetSymbolAddress((void**)&qe,  g_qe);
    cudaGetSymbolAddress((void**)&ke,  g_ke);
    cudaGetSymbolAddress((void**)&Araw, g_Araw);
    cudaGetSymbolAddress((void**)&alpha, g_alpha);
    cudaGetSymbolAddress((void**)&norm, g_norm);

    const float qscale = 0.125f; // DIM_HEAD^-0.5
    const long  smm    = (long)MLAND * MLAND;

    // 0. zero scratch (a3v accum, Araw accum, norm)
    zeros_k<<<(NHEADS * MLAND * DHEAD + 255) / 256, 256>>>(a3v, Araw, norm);

    // 1. qkv = dense @ w_qkv^T  [8192,1536]
    gemmT(true, NTOK, QKVW, DMODEL, 1.f, dense, DMODEL, 0, w_qkv, DMODEL, 0,
          qkv, QKVW, 0, 1);

    // 2. landmarks
    landmarks_k<<<(NHEADS * MLAND * DHEAD + 255) / 256, 256>>>(qkv, ql, kl);

    // 3. a1 = softmax(scale * q @ k_l^T)   [h,8192,256]
    gemmT(true, NTOK, MLAND, DHEAD, qscale,
          qkv, QKVW, DHEAD, kl, DHEAD, (long)MLAND * DHEAD,
          a1, MLAND, (long)NTOK * MLAND, NHEADS);
    softmax256_k<<<NHEADS * NTOK, 256>>>(a1);

    // 4. a2 = softmax(scale * q_l @ k_l^T) [h,256,256]
    gemmT(true, MLAND, MLAND, DHEAD, qscale,
          ql, DHEAD, (long)MLAND * DHEAD, kl, DHEAD, (long)MLAND * DHEAD,
          a2, MLAND, smm, NHEADS);
    softmax256_k<<<NHEADS * MLAND, 256>>>(a2);

    // 5. pinv init
    a2norm_k<<<NHEADS, 256>>>(a2, norm);
    zinit_k<<<(int)((NHEADS * smm + 255) / 256), 256>>>(a2, z, norm);

    // 6. pinv iterations (fp32 SIMT, fused epilogues)
    float* zin = z; float* zout = z2;
    dim3 gp(4, 4, NHEADS);
    for (int it = 0; it < PITERS; it++) {
        gemm64ep_k<<<gp, 256>>>(1.f, 0.f, a2, zin, xz, -1.f, 7.f, t1);     // xz, 7I-xz
        gemm64ep_k<<<gp, 256>>>(-1.f, 15.f, xz, t1, t2, 0.f, 0.f, nullptr); // 15I - xz@t1
        gemm64ep_k<<<gp, 256>>>(-1.f, 13.f, xz, t2, t1, 0.f, 0.f, nullptr); // 13I - xz@t2
        gemm64ep_k<<<gp, 256>>>(0.25f, 0.f, zin, t1, zout, 0.f, 0.f, nullptr);
        float* tmp = zin; zin = zout; zout = tmp;
    }
    float* zfin = zin;

    // 7. a3 = softmax(scale * q_l @ k^T)  [h,256,8192]
    gemmT(true, MLAND, NTOK, DHEAD, qscale,
          ql, DHEAD, (long)MLAND * DHEAD,
          qkv + NHEADS * DHEAD, QKVW, DHEAD,
          a3, NTOK, (long)MLAND * NTOK, NHEADS);
    softmax8192_k<<<NHEADS * MLAND, 1024>>>(a3);

    // 8. a3v = a3 @ v  [h,256,64]  (split-K 16, atomic; pre-zeroed)
    {
        dim3 g(1, MLAND / 128, NHEADS * 16);
        gemmT64_k<<<g, 256>>>(MLAND, NTOK, 1.f,
                              a3, NTOK, (long)MLAND * NTOK,
                              qkv + 2 * NHEADS * DHEAD, QKVW, DHEAD,
                              a3v, DHEAD, (long)MLAND * DHEAD, 16);
    }

    // 9. w1 = a1 @ zfin  [h,8192,256]
    gemmT(false, NTOK, MLAND, MLAND, 1.f,
          a1, MLAND, (long)NTOK * MLAND, zfin, MLAND, smm,
          w1, MLAND, (long)NTOK * MLAND, NHEADS);

    // 10. xh[n, h*64:+64] = w1 @ a3v
    {
        dim3 g(1, NTOK / 128, NHEADS);
        gemmT64_k<<<g, 256>>>(NTOK, MLAND, 1.f,
                              w1, MLAND, (long)NTOK * MLAND,
                              a3v, DHEAD, (long)MLAND * DHEAD,
                              xh, DMODEL, DHEAD, 1);
    }

    // 11. residual depthwise conv on v, added into xh
    convadd_k<<<(int)(((long)NTOK * DMODEL + 255) / 256), 256>>>(qkv, rker, xh);

    // 12. xg = xh @ w_out^T ; enc = xg + b_out + dense
    gemmT(true, NTOK, DMODEL, DMODEL, 1.f, xh, DMODEL, 0, w_out, DMODEL, 0,
          xg, DMODEL, 0, 1);
    enc_k<<<(int)(((long)NTOK * DMODEL + 255) / 256), 256>>>(xg, b_out, dense, enc);

    // 13. qe = enc @ wq ; ke = enc @ wk
    gemmT(false, NTOK, WPD, DMODEL, 1.f, enc, DMODEL, 0, wq, WPD, 0, qe, WPD, 0, 1);
    gemmT(false, NTOK, WPD, DMODEL, 1.f, enc, DMODEL, 0, wk, WPD, 0, ke, WPD, 0, 1);

    // 14. edge scores -> segment sum (Araw pre-zeroed)
    edge_k<<<(NEDGE + 7) / 8, 256>>>(qe, ke, arows, acols, avals, Araw);

    // 15. alpha = softmax(A_raw) over all N
    softmax_all_k<<<1, 1024>>>(Araw, alpha, NTOK);

    // 16. value = dense @ wv_w^T
    gemmT(true, NTOK, DMODEL, DMODEL, 1.f, dense, DMODEL, 0, wv_w, DMODEL, 0,
          val, DMODEL, 0, 1);

    // 17. final gated blend + A_raw copy
    final_k<<<(int)(((long)NTOK * DMODEL + 255) / 256), 256>>>(val, wv_b, alpha, enc, Araw, out);
}

// round 6
// speedup vs baseline: 1.6208x; 1.6208x over previous
#include <cuda_runtime.h>
#include <math.h>

// ---------------- problem constants ----------------
static const int NTOK   = 8192;   // N
static const int DMODEL = 512;    // D
static const int NHEADS = 8;
static const int DHEAD  = 64;
static const int MLAND  = 256;    // M landmarks
static const int LFOLD  = 32;     // N / M
static const int WPD    = 256;    // weight_params_dim
static const int NEDGE  = 262144; // E
static const int KCONV  = 33;
static const int QKVW   = 3 * NHEADS * DHEAD; // 1536
static const int PITERS = 6;

// ---------------- device scratch (BSS) ----------------
__device__ float g_qkv [NTOK * QKVW];
__device__ float g_ql  [NHEADS * MLAND * DHEAD];
__device__ float g_kl  [NHEADS * MLAND * DHEAD];
__device__ float g_a1  [(long)NHEADS * NTOK * MLAND];
__device__ float g_a2  [NHEADS * MLAND * MLAND];
__device__ float g_a3  [(long)NHEADS * MLAND * NTOK];
__device__ float g_z   [NHEADS * MLAND * MLAND];
__device__ float g_z2  [NHEADS * MLAND * MLAND];
__device__ float g_xz  [NHEADS * MLAND * MLAND];
__device__ float g_t1  [NHEADS * MLAND * MLAND];
__device__ float g_t2  [NHEADS * MLAND * MLAND];
__device__ float g_a3v [NHEADS * MLAND * DHEAD];
__device__ float g_w1  [(long)NHEADS * NTOK * MLAND];
__device__ float g_xh  [NTOK * DMODEL];
__device__ float g_xg  [NTOK * DMODEL];
__device__ float g_enc [NTOK * DMODEL];
__device__ float g_val [NTOK * DMODEL];
__device__ float g_qe  [NTOK * WPD];
__device__ float g_ke  [NTOK * WPD];
__device__ float g_Araw [NTOK];
__device__ float g_alpha[NTOK];
__device__ unsigned int g_norm[2];

// ---------------- tf32 / ptx helpers ----------------
__device__ __forceinline__ unsigned f2tf(float x) {
    unsigned u;
    asm("cvt.rna.tf32.f32 %0, %1;" : "=r"(u) : "f"(x));
    return u;
}
__device__ __forceinline__ void split_u(unsigned x, unsigned& hi, unsigned& lo) {
    float f = __uint_as_float(x);
    hi = f2tf(f);
    lo = f2tf(f - __uint_as_float(hi));
}
__device__ __forceinline__ void mma8(float* c, const unsigned* a, const unsigned* b) {
    asm volatile(
        "mma.sync.aligned.m16n8k8.row.col.f32.tf32.tf32.f32 "
        "{%0,%1,%2,%3}, {%4,%5,%6,%7}, {%8,%9}, {%0,%1,%2,%3};"
        : "+f"(c[0]), "+f"(c[1]), "+f"(c[2]), "+f"(c[3])
        : "r"(a[0]), "r"(a[1]), "r"(a[2]), "r"(a[3]), "r"(b[0]), "r"(b[1]));
}
__device__ __forceinline__ void ldsm4(unsigned& r0, unsigned& r1, unsigned& r2,
                                      unsigned& r3, unsigned addr) {
    asm volatile("ldmatrix.sync.aligned.m8n8.x4.shared.b16 {%0,%1,%2,%3}, [%4];"
        : "=r"(r0), "=r"(r1), "=r"(r2), "=r"(r3) : "r"(addr));
}
__device__ __forceinline__ unsigned sptr(const void* p) {
    return (unsigned)__cvta_generic_to_shared(p);
}
#define CP16(d, s)  asm volatile("cp.async.ca.shared.global [%0], [%1], 16;" :: "r"(d), "l"(s))
#define CP4(d, s)   asm volatile("cp.async.ca.shared.global [%0], [%1], 4;"  :: "r"(d), "l"(s))
#define CPCOMMIT()  asm volatile("cp.async.commit_group;")
#define CPWAIT1()   asm volatile("cp.async.wait_group 1;")
#define CPWAIT0()   asm volatile("cp.async.wait_group 0;")

// padded physical row index: insert one 16B slot every 8 rows (bank spread)
__device__ __forceinline__ int prp(int r) { return r + (r >> 3); }

static const int SROWS = 144;  // prp(127)=142 < 144
struct StageT { float A[2][2][SROWS][4]; float B[2][2][SROWS][4]; };

// =====================================================================
// gemmT2: tf32x3 tensor GEMM, raw-fp32 smem + ldmatrix + cp.async 2-stage.
// CTA tile 128 x BN x 16, 256 threads (8 warps 4x2), warp tile 32 x BN/2.
// C = alpha * A[M,K] @ op(B). TB: B=[N,K]. !TB: B=[K,N].
// kSplit>1: atomicAdd into pre-zeroed C. REQUIRES M%128==0, N%BN==0,
// (K/kSplit)%16==0, lda/ldb%4==0, 16B-aligned base pointers.
// =====================================================================
template<bool TB, int BN>
__global__ __launch_bounds__(256, 2)
void gemmT2_k(int M, int N, int K, float alpha,
              const float* __restrict__ A, int lda, long sA,
              const float* __restrict__ B, int ldb, long sB,
              float* __restrict__ C, int ldc, long sC, int kSplit)
{
    constexpr int WNT = BN / 16;  // n-tiles (8 cols each) per warp
    constexpr int NP  = WNT / 2;  // ldmatrix x4 pairs
    constexpr int NB  = (BN == 128) ? 8 : 4; // NT fill elems/thread

    int bz = blockIdx.z;
    int batch = bz / kSplit, ks = bz - batch * kSplit;
    A += (long)batch * sA; B += (long)batch * sB; C += (long)batch * sC;
    const int chunk = K / kSplit;
    const int k0s = ks * chunk;
    const int T = chunk >> 4;

    const int row0 = blockIdx.y * 128;
    const int col0 = blockIdx.x * BN;
    const int tid  = threadIdx.x;
    const int lane = tid & 31, w = tid >> 5, wr = w >> 1, wc = w & 1;

    __shared__ __align__(16) StageT sm[2];
    const unsigned stageSz = (unsigned)sizeof(StageT);

    // ---- fill precompute ----
    const int ar = tid >> 1, akt = tid & 1;
    const float* aSrc = A + (long)(row0 + ar) * lda + akt * 8;
    const unsigned aD0 = sptr(&sm[0].A[akt][0][prp(ar)][0]);
    const unsigned aD1 = sptr(&sm[0].A[akt][1][prp(ar)][0]);

    const float* bSrc;
    unsigned bD0 = 0, bD1 = 0;
    unsigned bDst[8];
    if (TB) {
        int bn = tid >> 1, bkt = tid & 1;
        bSrc = B + (long)(col0 + bn) * ldb + bkt * 8;
        bD0 = sptr(&sm[0].B[bkt][0][prp(bn)][0]);
        bD1 = sptr(&sm[0].B[bkt][1][prp(bn)][0]);
    } else {
        int n  = tid & (BN - 1);
        int kb = (tid >> ((BN == 128) ? 7 : 6)) * NB;
        bSrc = B + (long)kb * ldb + col0 + n;
        #pragma unroll
        for (int j = 0; j < NB; j++) {
            int kk = kb + j;
            bDst[j] = sptr(&sm[0].B[kk >> 3][(kk >> 2) & 1][prp(n)][kk & 3]);
        }
    }

    auto fill = [&](int kAbs, int s) {
        unsigned so = s * stageSz;
        CP16(aD0 + so, aSrc + kAbs);
        CP16(aD1 + so, aSrc + kAbs + 4);
        if (TB) {
            CP16(bD0 + so, bSrc + kAbs);
            CP16(bD1 + so, bSrc + kAbs + 4);
        } else {
            #pragma unroll
            for (int j = 0; j < NB; j++)
                CP4(bDst[j] + so, bSrc + (long)(kAbs + j) * ldb);
        }
    };

    // ---- ldmatrix address precompute ----
    const int aRow = wr * 32 + (lane & 15);
    const int aKj  = lane >> 4;
    unsigned aAdr[2][2];
    #pragma unroll
    for (int kt = 0; kt < 2; kt++)
        #pragma unroll
        for (int rt = 0; rt < 2; rt++)
            aAdr[kt][rt] = sptr(&sm[0].A[kt][aKj][prp(aRow + rt * 16)][0]);

    const int bKj  = (lane >> 3) & 1;
    const int bRow = wc * (BN / 2) + ((lane & 7) | ((lane & 16) >> 1));
    unsigned bAdr[2][NP];
    #pragma unroll
    for (int kt = 0; kt < 2; kt++)
        #pragma unroll
        for (int p = 0; p < NP; p++)
            bAdr[kt][p] = sptr(&sm[0].B[kt][bKj][prp(bRow + p * 16)][0]);

    float acc[2][WNT][4];
    #pragma unroll
    for (int i = 0; i < 2; i++)
        #pragma unroll
        for (int j = 0; j < WNT; j++)
            #pragma unroll
            for (int v = 0; v < 4; v++) acc[i][j][v] = 0.f;

    auto compute = [&](int s) {
        unsigned so = s * stageSz;
        #pragma unroll
        for (int kt = 0; kt < 2; kt++) {
            unsigned ah[2][4], al[2][4];
            #pragma unroll
            for (int rt = 0; rt < 2; rt++) {
                unsigned r0, r1, r2, r3;
                ldsm4(r0, r1, r2, r3, aAdr[kt][rt] + so);
                split_u(r0, ah[rt][0], al[rt][0]);
                split_u(r1, ah[rt][1], al[rt][1]);
                split_u(r2, ah[rt][2], al[rt][2]);
                split_u(r3, ah[rt][3], al[rt][3]);
            }
            #pragma unroll
            for (int p = 0; p < NP; p++) {
                unsigned r0, r1, r2, r3;
                ldsm4(r0, r1, r2, r3, bAdr[kt][p] + so);
                unsigned bh0[2], bl0[2], bh1[2], bl1[2];
                split_u(r0, bh0[0], bl0[0]);
                split_u(r1, bh0[1], bl0[1]);
                split_u(r2, bh1[0], bl1[0]);
                split_u(r3, bh1[1], bl1[1]);
                #pragma unroll
                for (int rt = 0; rt < 2; rt++) {
                    mma8(acc[rt][2 * p],     ah[rt], bh0);
                    mma8(acc[rt][2 * p],     al[rt], bh0);
                    mma8(acc[rt][2 * p],     ah[rt], bl0);
                    mma8(acc[rt][2 * p + 1], ah[rt], bh1);
                    mma8(acc[rt][2 * p + 1], al[rt], bh1);
                    mma8(acc[rt][2 * p + 1], ah[rt], bl1);
                }
            }
        }
    };

    // ---- 2-stage pipelined mainloop ----
    fill(k0s, 0);
    CPCOMMIT();
    int stage = 0;
    for (int t = 0; t < T; t++) {
        if (t + 1 < T) {
            fill(k0s + (t + 1) * 16, stage ^ 1);
            CPCOMMIT();
            CPWAIT1();
        } else {
            CPWAIT0();
        }
        __syncthreads();
        compute(stage);
        __syncthreads();
        stage ^= 1;
    }

    // ---- epilogue ----
    const int g = lane >> 2, tg = lane & 3;
    #pragma unroll
    for (int rt = 0; rt < 2; rt++) {
        #pragma unroll
        for (int n2 = 0; n2 < WNT; n2++) {
            int gr = row0 + wr * 32 + rt * 16 + g;
            int gc = col0 + wc * (BN / 2) + n2 * 8 + tg * 2;
            float* c = acc[rt][n2];
            float* p0 = C + (long)gr * ldc + gc;
            float* p1 = p0 + 8 * (long)ldc;
            if (kSplit > 1) {
                atomicAdd(p0 + 0, alpha * c[0]); atomicAdd(p0 + 1, alpha * c[1]);
                atomicAdd(p1 + 0, alpha * c[2]); atomicAdd(p1 + 1, alpha * c[3]);
            } else {
                p0[0] = alpha * c[0]; p0[1] = alpha * c[1];
                p1[0] = alpha * c[2]; p1[1] = alpha * c[3];
            }
        }
    }
}

static void gemmT(bool tb, int M, int N, int K, float alpha,
                  const float* A, int lda, long sA,
                  const float* B, int ldb, long sB,
                  float* C, int ldc, long sC, int batch)
{
    dim3 g(N / 128, M / 128, batch);
    if (tb) gemmT2_k<true, 128><<<g, 256>>>(M, N, K, alpha, A, lda, sA,
                                            B, ldb, sB, C, ldc, sC, 1);
    else    gemmT2_k<false, 128><<<g, 256>>>(M, N, K, alpha, A, lda, sA,
                                             B, ldb, sB, C, ldc, sC, 1);
}

static void gemmT64(int M, int K, float alpha,
                    const float* A, int lda, long sA,
                    const float* B, int ldb, long sB,
                    float* C, int ldc, long sC, int batch, int kSplit)
{
    dim3 g(1, M / 128, batch * kSplit);
    gemmT2_k<false, 64><<<g, 256>>>(M, 64, K, alpha, A, lda, sA,
                                    B, ldb, sB, C, ldc, sC, kSplit);
}

// =====================================================================
// gemm64ep: fp32 SIMT 256x256x256 batched GEMM (pinv), NT, 64x64 tile,
// fused epilogue:  C = alpha*(A@B) + diag*I,  optional C2 likewise.
// =====================================================================
__global__ __launch_bounds__(256)
void gemm64ep_k(float alpha, float diag,
                const float* __restrict__ A, const float* __restrict__ B,
                float* __restrict__ C,
                float alpha2, float diag2, float* __restrict__ C2)
{
    const long sb = (long)MLAND * MLAND;
    A += blockIdx.z * sb;
    B += blockIdx.z * sb;
    C += blockIdx.z * sb;
    if (C2) C2 += blockIdx.z * sb;

    __shared__ float As[64 * 17];
    __shared__ float Bs[16 * 64];

    int tid = threadIdx.x;
    int row0 = blockIdx.y * 64;
    int col0 = blockIdx.x * 64;
    int tx = tid & 15, ty = tid >> 4;

    float acc[4][4] = {};

    for (int kk = 0; kk < 256; kk += 16) {
        #pragma unroll
        for (int i = 0; i < 4; i++) {
            int e = tid + i * 256;
            int r = e >> 4, c = e & 15;
            As[r * 17 + c] = A[(long)(row0 + r) * 256 + kk + c];
        }
        #pragma unroll
        for (int i = 0; i < 4; i++) {
            int e = tid + i * 256;
            int c = e >> 6, n = e & 63;
            Bs[c * 64 + n] = B[(long)(kk + c) * 256 + col0 + n];
        }
        __syncthreads();
        #pragma unroll
        for (int c = 0; c < 16; c++) {
            float a[4], b[4];
            #pragma unroll
            for (int i = 0; i < 4; i++) a[i] = As[(ty * 4 + i) * 17 + c];
            #pragma unroll
            for (int j = 0; j < 4; j++) b[j] = Bs[c * 64 + tx * 4 + j];
            #pragma unroll
            for (int i = 0; i < 4; i++)
                #pragma unroll
                for (int j = 0; j < 4; j++)
                    acc[i][j] = fmaf(a[i], b[j], acc[i][j]);
        }
        __syncthreads();
    }
    #pragma unroll
    for (int i = 0; i < 4; i++) {
        int gr = row0 + ty * 4 + i;
        #pragma unroll
        for (int j = 0; j < 4; j++) {
            int gc = col0 + tx * 4 + j;
            float d = (gr == gc) ? 1.f : 0.f;
            C[(long)gr * 256 + gc] = alpha * acc[i][j] + diag * d;
            if (C2) C2[(long)gr * 256 + gc] = alpha2 * acc[i][j] + diag2 * d;
        }
    }
}

// ---------------- small kernels ----------------
__global__ void zeros_k(float* a3v, float* Araw, unsigned int* norm)
{
    long i = (long)blockIdx.x * 256 + threadIdx.x;
    if (i < NHEADS * MLAND * DHEAD) a3v[i] = 0.f;
    if (i < NTOK) Araw[i] = 0.f;
    if (i < 2) norm[i] = 0u;
}

__global__ void landmarks_k(const float* __restrict__ qkv,
                            float* __restrict__ ql, float* __restrict__ kl)
{
    int idx = blockIdx.x * blockDim.x + threadIdx.x;
    if (idx >= NHEADS * MLAND * DHEAD) return;
    int d = idx & 63; int j = (idx >> 6) & 255; int h = idx >> 14;
    const float* qp = qkv + (long)(j * LFOLD) * QKVW + h * DHEAD + d;
    const float* kp = qp + NHEADS * DHEAD;
    float sq = 0.f, sk = 0.f;
    #pragma unroll 4
    for (int t = 0; t < LFOLD; t++) {
        sq += qp[(long)t * QKVW];
        sk += kp[(long)t * QKVW];
    }
    ql[idx] = sq * (1.f / LFOLD);
    kl[idx] = sk * (1.f / LFOLD);
}

__global__ __launch_bounds__(256)
void softmax256_k(float* __restrict__ X)
{
    float* x = X + (long)blockIdx.x * 256;
    int tid = threadIdx.x;
    __shared__ float sm[8];
    float v = x[tid];
    float m = v;
    #pragma unroll
    for (int o = 16; o; o >>= 1) m = fmaxf(m, __shfl_xor_sync(0xffffffffu, m, o));
    if ((tid & 31) == 0) sm[tid >> 5] = m;
    __syncthreads();
    m = sm[0];
    #pragma unroll
    for (int i = 1; i < 8; i++) m = fmaxf(m, sm[i]);
    float e = __expf(v - m);
    float s = e;
    #pragma unroll
    for (int o = 16; o; o >>= 1) s += __shfl_xor_sync(0xffffffffu, s, o);
    __syncthreads();
    if ((tid & 31) == 0) sm[tid >> 5] = s;
    __syncthreads();
    s = sm[0];
    #pragma unroll
    for (int i = 1; i < 8; i++) s += sm[i];
    x[tid] = e * (1.f / s);
}

__global__ __launch_bounds__(1024)
void softmax8192_k(float* __restrict__ X)
{
    float* x = X + (long)blockIdx.x * 8192;
    int tid = threadIdx.x;
    __shared__ float sm[32];
    float4 v0 = *(const float4*)(x + tid * 8);
    float4 v1 = *(const float4*)(x + tid * 8 + 4);
    float m = fmaxf(fmaxf(fmaxf(v0.x, v0.y), fmaxf(v0.z, v0.w)),
                    fmaxf(fmaxf(v1.x, v1.y), fmaxf(v1.z, v1.w)));
    #pragma unroll
    for (int o = 16; o; o >>= 1) m = fmaxf(m, __shfl_xor_sync(0xffffffffu, m, o));
    if ((tid & 31) == 0) sm[tid >> 5] = m;
    __syncthreads();
    m = sm[0];
    #pragma unroll
    for (int i = 1; i < 32; i++) m = fmaxf(m, sm[i]);
    float e0 = __expf(v0.x - m), e1 = __expf(v0.y - m);
    float e2 = __expf(v0.z - m), e3 = __expf(v0.w - m);
    float e4 = __expf(v1.x - m), e5 = __expf(v1.y - m);
    float e6 = __expf(v1.z - m), e7 = __expf(v1.w - m);
    float s = ((e0 + e1) + (e2 + e3)) + ((e4 + e5) + (e6 + e7));
    #pragma unroll
    for (int o = 16; o; o >>= 1) s += __shfl_xor_sync(0xffffffffu, s, o);
    __syncthreads();
    if ((tid & 31) == 0) sm[tid >> 5] = s;
    __syncthreads();
    s = sm[0];
    #pragma unroll
    for (int i = 1; i < 32; i++) s += sm[i];
    float inv = 1.f / s;
    *(float4*)(x + tid * 8)     = make_float4(e0 * inv, e1 * inv, e2 * inv, e3 * inv);
    *(float4*)(x + tid * 8 + 4) = make_float4(e4 * inv, e5 * inv, e6 * inv, e7 * inv);
}

__global__ void a2norm_k(const float* __restrict__ a2, unsigned int* norm)
{
    int h = blockIdx.x; int t = threadIdx.x;
    const float* x = a2 + (long)h * MLAND * MLAND;
    float rs = 0.f, cs = 0.f;
    for (int j = 0; j < MLAND; j++) {
        rs += fabsf(x[t * MLAND + j]);
        cs += fabsf(x[j * MLAND + t]);
    }
    __shared__ float s1[8], s2[8];
    for (int o = 16; o; o >>= 1) {
        rs = fmaxf(rs, __shfl_xor_sync(0xffffffffu, rs, o));
        cs = fmaxf(cs, __shfl_xor_sync(0xffffffffu, cs, o));
    }
    if ((t & 31) == 0) { s1[t >> 5] = rs; s2[t >> 5] = cs; }
    __syncthreads();
    if (t == 0) {
        rs = s1[0]; cs = s2[0];
        for (int w = 1; w < 8; w++) { rs = fmaxf(rs, s1[w]); cs = fmaxf(cs, s2[w]); }
        atomicMax(&norm[0], __float_as_uint(rs));
        atomicMax(&norm[1], __float_as_uint(cs));
    }
}

__global__ void zinit_k(const float* __restrict__ a2, float* __restrict__ z,
                        const unsigned int* __restrict__ norm)
{
    long idx = (long)blockIdx.x * 256 + threadIdx.x;
    if (idx >= (long)NHEADS * MLAND * MLAND) return;
    float inv = 1.f / (__uint_as_float(norm[0]) * __uint_as_float(norm[1]));
    int j = idx & 255; int i = (idx >> 8) & 255; long h = idx >> 16;
    z[idx] = a2[h * 65536 + (long)j * 256 + i] * inv;
}

__global__ void convadd_k(const float* __restrict__ qkv,
                          const float* __restrict__ rker,
                          float* __restrict__ xh)
{
    long idx = (long)blockIdx.x * 256 + threadIdx.x;
    if (idx >= (long)NTOK * DMODEL) return;
    int col = idx & 511; long n = idx >> 9;
    int h = col >> 6;
    float s = 0.f;
    #pragma unroll
    for (int t = 0; t < KCONV; t++) {
        long r = n + t - KCONV / 2;
        if (r >= 0 && r < NTOK)
            s += rker[h * KCONV + t] * qkv[r * QKVW + 2 * NHEADS * DHEAD + col];
    }
    xh[idx] += s;
}

__global__ void enc_k(const float* __restrict__ xg, const float* __restrict__ bout,
                      const float* __restrict__ dense, float* __restrict__ enc)
{
    long idx = (long)blockIdx.x * 256 + threadIdx.x;
    if (idx >= (long)NTOK * DMODEL) return;
    int col = idx & 511;
    enc[idx] = xg[idx] + bout[col] + dense[idx];
}

__global__ void edge_k(const float* __restrict__ qe, const float* __restrict__ ke,
                       const int* __restrict__ rows, const int* __restrict__ cols,
                       const float* __restrict__ vals, float* __restrict__ Araw)
{
    int e = blockIdx.x * (blockDim.x >> 5) + (threadIdx.x >> 5);
    int lane = threadIdx.x & 31;
    if (e >= NEDGE) return;
    int r = rows[e], c = cols[e];
    const float4* qr = (const float4*)(qe + (long)r * WPD);
    const float4* kc = (const float4*)(ke + (long)c * WPD);
    float s = 0.f;
    #pragma unroll
    for (int i = lane; i < WPD / 4; i += 32) {
        float4 a = qr[i], b = kc[i];
        s += a.x * b.x + a.y * b.y + a.z * b.z + a.w * b.w;
    }
    for (int o = 16; o; o >>= 1) s += __shfl_xor_sync(0xffffffffu, s, o);
    if (lane == 0) atomicAdd(&Araw[r], s * 0.0625f * vals[e]);
}

__global__ void softmax_all_k(const float* __restrict__ A, float* __restrict__ alpha, int n)
{
    __shared__ float sm[32];
    int tid = threadIdx.x; // 1024
    float m = -1e30f;
    for (int i = tid; i < n; i += 1024) m = fmaxf(m, A[i]);
    for (int o = 16; o; o >>= 1) m = fmaxf(m, __shfl_xor_sync(0xffffffffu, m, o));
    if ((tid & 31) == 0) sm[tid >> 5] = m;
    __syncthreads();
    if (tid == 0) { float bm = sm[0]; for (int w = 1; w < 32; w++) bm = fmaxf(bm, sm[w]); sm[0] = bm; }
    __syncthreads();
    m = sm[0];
    __syncthreads();
    float s = 0.f;
    for (int i = tid; i < n; i += 1024) s += __expf(A[i] - m);
    for (int o = 16; o; o >>= 1) s += __shfl_xor_sync(0xffffffffu, s, o);
    if ((tid & 31) == 0) sm[tid >> 5] = s;
    __syncthreads();
    if (tid == 0) { float bs = 0.f; for (int w = 0; w < 32; w++) bs += sm[w]; sm[0] = bs; }
    __syncthreads();
    float inv = 1.f / sm[0];
    for (int i = tid; i < n; i += 1024) alpha[i] = __expf(A[i] - m) * inv;
}

__global__ void final_k(const float* __restrict__ val, const float* __restrict__ wvb,
                        const float* __restrict__ alpha, const float* __restrict__ enc,
                        const float* __restrict__ Araw, float* __restrict__ out)
{
    long idx = (long)blockIdx.x * 256 + threadIdx.x;
    long total = (long)NTOK * DMODEL;
    if (idx < total) {
        int col = idx & 511; long n = idx >> 9;
        float v = val[idx] + wvb[col];
        float xl = alpha[n] * v;
        float w = 1.f / (1.f + __expf(xl)); // sigmoid(-xl)
        float sq = w * w;
        float e = enc[idx];
        out[idx] = xl * 2.f * sq + 2.f * e * (1.f - sq);
    }
    if (idx < NTOK) out[total + idx] = Araw[idx];
}

// ---------------- driver ----------------
extern "C" void kernel_launch(void* const* d_in, const int* in_sizes, int n_in,
                              void* d_out, int out_size)
{
    const float* dense  = (const float*)d_in[0];
    const int*   arows  = (const int*)  d_in[1];
    const int*   acols  = (const int*)  d_in[2];
    const float* avals  = (const float*)d_in[3];
    const float* wq     = (const float*)d_in[4];
    const float* wk     = (const float*)d_in[5];
    const float* w_qkv  = (const float*)d_in[6];
    const float* w_out  = (const float*)d_in[7];
    const float* b_out  = (const float*)d_in[8];
    const float* rker   = (const float*)d_in[9];
    const float* wv_w   = (const float*)d_in[10];
    const float* wv_b   = (const float*)d_in[11];
    float* out = (float*)d_out;

    float *qkv, *ql, *kl, *a1, *a2, *a3, *z, *z2, *xz, *t1, *t2, *a3v, *w1;
    float *xh, *xg, *enc, *val, *qe, *ke, *Araw, *alpha;
    unsigned int* norm;
    cudaGetSymbolAddress((void**)&qkv, g_qkv);
    cudaGetSymbolAddress((void**)&ql,  g_ql);
    cudaGetSymbolAddress((void**)&kl,  g_kl);
    cudaGetSymbolAddress((void**)&a1,  g_a1);
    cudaGetSymbolAddress((void**)&a2,  g_a2);
    cudaGetSymbolAddress((void**)&a3,  g_a3);
    cudaGetSymbolAddress((void**)&z,   g_z);
    cudaGetSymbolAddress((void**)&z2,  g_z2);
    cudaGetSymbolAddress((void**)&xz,  g_xz);
    cudaGetSymbolAddress((void**)&t1,  g_t1);
    cudaGetSymbolAddress((void**)&t2,  g_t2);
    cudaGetSymbolAddress((void**)&a3v, g_a3v);
    cudaGetSymbolAddress((void**)&w1,  g_w1);
    cudaGetSymbolAddress((void**)&xh,  g_xh);
    cudaGetSymbolAddress((void**)&xg,  g_xg);
    cudaGetSymbolAddress((void**)&enc, g_enc);
    cudaGetSymbolAddress((void**)&val, g_val);
    cudaGetSymbolAddress((void**)&qe,  g_qe);
    cudaGetSymbolAddress((void**)&ke,  g_ke);
    cudaGetSymbolAddress((void**)&Araw, g_Araw);
    cudaGetSymbolAddress((void**)&alpha, g_alpha);
    cudaGetSymbolAddress((void**)&norm, g_norm);

    const float qscale = 0.125f; // DIM_HEAD^-0.5
    const long  smm    = (long)MLAND * MLAND;

    // 0. zero scratch (a3v accum, Araw accum, norm)
    zeros_k<<<(NHEADS * MLAND * DHEAD + 255) / 256, 256>>>(a3v, Araw, norm);

    // 1. qkv = dense @ w_qkv^T  [8192,1536]
    gemmT(true, NTOK, QKVW, DMODEL, 1.f, dense, DMODEL, 0, w_qkv, DMODEL, 0,
          qkv, QKVW, 0, 1);

    // 2. landmarks
    landmarks_k<<<(NHEADS * MLAND * DHEAD + 255) / 256, 256>>>(qkv, ql, kl);

    // 3. a1 = softmax(scale * q @ k_l^T)   [h,8192,256]
    gemmT(true, NTOK, MLAND, DHEAD, qscale,
          qkv, QKVW, DHEAD, kl, DHEAD, (long)MLAND * DHEAD,
          a1, MLAND, (long)NTOK * MLAND, NHEADS);
    softmax256_k<<<NHEADS * NTOK, 256>>>(a1);

    // 4. a2 = softmax(scale * q_l @ k_l^T) [h,256,256]
    gemmT(true, MLAND, MLAND, DHEAD, qscale,
          ql, DHEAD, (long)MLAND * DHEAD, kl, DHEAD, (long)MLAND * DHEAD,
          a2, MLAND, smm, NHEADS);
    softmax256_k<<<NHEADS * MLAND, 256>>>(a2);

    // 5. pinv init
    a2norm_k<<<NHEADS, 256>>>(a2, norm);
    zinit_k<<<(int)((NHEADS * smm + 255) / 256), 256>>>(a2, z, norm);

    // 6. pinv iterations (fp32 SIMT, fused epilogues)
    float* zin = z; float* zout = z2;
    dim3 gp(4, 4, NHEADS);
    for (int it = 0; it < PITERS; it++) {
        gemm64ep_k<<<gp, 256>>>(1.f, 0.f, a2, zin, xz, -1.f, 7.f, t1);      // xz, 7I-xz
        gemm64ep_k<<<gp, 256>>>(-1.f, 15.f, xz, t1, t2, 0.f, 0.f, nullptr); // 15I - xz@t1
        gemm64ep_k<<<gp, 256>>>(-1.f, 13.f, xz, t2, t1, 0.f, 0.f, nullptr); // 13I - xz@t2
        gemm64ep_k<<<gp, 256>>>(0.25f, 0.f, zin, t1, zout, 0.f, 0.f, nullptr);
        float* tmp = zin; zin = zout; zout = tmp;
    }
    float* zfin = zin;

    // 7. a3 = softmax(scale * q_l @ k^T)  [h,256,8192]
    gemmT(true, MLAND, NTOK, DHEAD, qscale,
          ql, DHEAD, (long)MLAND * DHEAD,
          qkv + NHEADS * DHEAD, QKVW, DHEAD,
          a3, NTOK, (long)MLAND * NTOK, NHEADS);
    softmax8192_k<<<NHEADS * MLAND, 1024>>>(a3);

    // 8. a3v = a3 @ v  [h,256,64]  (split-K 16, atomic; pre-zeroed)
    gemmT64(MLAND, NTOK, 1.f,
            a3, NTOK, (long)MLAND * NTOK,
            qkv + 2 * NHEADS * DHEAD, QKVW, DHEAD,
            a3v, DHEAD, (long)MLAND * DHEAD, NHEADS, 16);

    // 9. w1 = a1 @ zfin  [h,8192,256]
    gemmT(false, NTOK, MLAND, MLAND, 1.f,
          a1, MLAND, (long)NTOK * MLAND, zfin, MLAND, smm,
          w1, MLAND, (long)NTOK * MLAND, NHEADS);

    // 10. xh[n, h*64:+64] = w1 @ a3v
    gemmT64(NTOK, MLAND, 1.f,
            w1, MLAND, (long)NTOK * MLAND,
            a3v, DHEAD, (long)MLAND * DHEAD,
            xh, DMODEL, DHEAD, NHEADS, 1);

    // 11. residual depthwise conv on v, added into xh
    convadd_k<<<(int)(((long)NTOK * DMODEL + 255) / 256), 256>>>(qkv, rker, xh);

    // 12. xg = xh @ w_out^T ; enc = xg + b_out + dense
    gemmT(true, NTOK, DMODEL, DMODEL, 1.f, xh, DMODEL, 0, w_out, DMODEL, 0,
          xg, DMODEL, 0, 1);
    enc_k<<<(int)(((long)NTOK * DMODEL + 255) / 256), 256>>>(xg, b_out, dense, enc);

    // 13. qe = enc @ wq ; ke = enc @ wk
    gemmT(false, NTOK, WPD, DMODEL, 1.f, enc, DMODEL, 0, wq, WPD, 0, qe, WPD, 0, 1);
    gemmT(false, NTOK, WPD, DMODEL, 1.f, enc, DMODEL, 0, wk, WPD, 0, ke, WPD, 0, 1);

    // 14. edge scores -> segment sum (Araw pre-zeroed)
    edge_k<<<(NEDGE + 7) / 8, 256>>>(qe, ke, arows, acols, avals, Araw);

    // 15. alpha = softmax(A_raw) over all N
    softmax_all_k<<<1, 1024>>>(Araw, alpha, NTOK);

    // 16. value = dense @ wv_w^T
    gemmT(true, NTOK, DMODEL, DMODEL, 1.f, dense, DMODEL, 0, wv_w, DMODEL, 0,
          val, DMODEL, 0, 1);

    // 17. final gated blend + A_raw copy
    final_k<<<(int)(((long)NTOK * DMODEL + 255) / 256), 256>>>(val, wv_b, alpha, enc, Araw, out);
}